// round 9
// baseline (speedup 1.0000x reference)
#include <cuda_runtime.h>
#include <cuda_fp16.h>

#define NN 10000
#define NE 4000
#define MAXM (4 * 1024 * 1024)
#define PAD 64  // 256B stride between atomic counters -> spreads across all LTS slices

// ---------------- device scratch (zero-initialized at module load) ----------------
__device__ float g_VT[128 * 128];
__device__ float g_cc[128];
__device__ __half g_Y[NN * 128];
__device__ __half g_emean[2 * NE * 64];
__device__ int g_ecnt[2 * NE * PAD];   // zeroed by scan after reading (invariant)
__device__ int g_epos[2 * NE * PAD];
__device__ int g_eptr[2 * NE + 1];
__device__ int g_n1cnt[NN * PAD];      // zeroed by scan after reading (invariant)
__device__ int g_n1pos[NN * PAD];
__device__ int g_n1ptr[NN + 1];
__device__ int g_n2ptr[NN + 1];        // fully rewritten by hist each call
__device__ int g_emem[MAXM];
__device__ int g_nmem1[MAXM];

// ---------------- side-stream plumbing (created once, before harness checkpoints) ----
struct HxPlumbing {
    cudaStream_t side;
    cudaEvent_t ev_fork, ev_gemm;
    HxPlumbing() {
        cudaStreamCreateWithFlags(&side, cudaStreamNonBlocking);
        cudaEventCreateWithFlags(&ev_fork, cudaEventDisableTiming);
        cudaEventCreateWithFlags(&ev_gemm, cudaEventDisableTiming);
    }
};
static HxPlumbing hx;

// ---------------- fold weights (side stream) ----------------
__global__ void fold_kernel(const float* __restrict__ W1, const float* __restrict__ b1,
                            const float* __restrict__ W2, const float* __restrict__ b2,
                            const float* __restrict__ Wout) {
    int bb = blockIdx.x;
    if (bb < 64) {
        int idx = bb * 256 + threadIdx.x;
        int j = idx >> 7, k = idx & 127;
        int s = j >> 6, jo = j & 63;
        const float* W = s ? W2 : W1;
        float sum = 0.f;
#pragma unroll 8
        for (int h = 0; h < 128; h++) sum = fmaf(Wout[jo * 128 + h], W[h * 128 + k], sum);
        g_VT[k * 128 + j] = sum;
    } else {
        int j = threadIdx.x;
        if (j < 128) {
            int s = j >> 6, jo = j & 63;
            const float* b = s ? b2 : b1;
            float sum = 0.f;
#pragma unroll 8
            for (int h = 0; h < 128; h++) sum = fmaf(Wout[jo * 128 + h], b[h], sum);
            g_cc[j] = sum;
        }
    }
}

// ---------------- GEMM (side stream): Y = x @ Vcat^T + cc, fp16 out ----------------
#define GEMM_BLOCKS ((NN + 31) / 32)  // 313

#define FMA4(a, sc, v)                 \
    a.x = fmaf(sc, v.x, a.x);          \
    a.y = fmaf(sc, v.y, a.y);          \
    a.z = fmaf(sc, v.z, a.z);          \
    a.w = fmaf(sc, v.w, a.w);

__global__ __launch_bounds__(256) void gemm_kernel(const float* __restrict__ x) {
    int tx = threadIdx.x & 31;
    int ty = threadIdx.x >> 5;
    int row0 = blockIdx.x * 32 + ty * 4;
    const float4* x4 = (const float4*)x;
    const float4* v4 = (const float4*)g_VT;

    int rb0 = (row0 + 0 < NN ? row0 + 0 : NN - 1) * 32;
    int rb1 = (row0 + 1 < NN ? row0 + 1 : NN - 1) * 32;
    int rb2 = (row0 + 2 < NN ? row0 + 2 : NN - 1) * 32;
    int rb3 = (row0 + 3 < NN ? row0 + 3 : NN - 1) * 32;

    float4 a0 = make_float4(0.f, 0.f, 0.f, 0.f), a1 = a0, a2 = a0, a3 = a0;

#pragma unroll 4
    for (int k4 = 0; k4 < 32; k4++) {
        float4 v0 = v4[(4 * k4 + 0) * 32 + tx];
        float4 v1 = v4[(4 * k4 + 1) * 32 + tx];
        float4 v2 = v4[(4 * k4 + 2) * 32 + tx];
        float4 v3 = v4[(4 * k4 + 3) * 32 + tx];
        float4 q;
        q = x4[rb0 + k4];
        FMA4(a0, q.x, v0); FMA4(a0, q.y, v1); FMA4(a0, q.z, v2); FMA4(a0, q.w, v3);
        q = x4[rb1 + k4];
        FMA4(a1, q.x, v0); FMA4(a1, q.y, v1); FMA4(a1, q.z, v2); FMA4(a1, q.w, v3);
        q = x4[rb2 + k4];
        FMA4(a2, q.x, v0); FMA4(a2, q.y, v1); FMA4(a2, q.z, v2); FMA4(a2, q.w, v3);
        q = x4[rb3 + k4];
        FMA4(a3, q.x, v0); FMA4(a3, q.y, v1); FMA4(a3, q.z, v2); FMA4(a3, q.w, v3);
    }
    float4 c = ((const float4*)g_cc)[tx];
    a0.x += c.x; a0.y += c.y; a0.z += c.z; a0.w += c.w;
    a1.x += c.x; a1.y += c.y; a1.z += c.z; a1.w += c.w;
    a2.x += c.x; a2.y += c.y; a2.z += c.z; a2.w += c.w;
    a3.x += c.x; a3.y += c.y; a3.z += c.z; a3.w += c.w;

    union { __half2 h[2]; uint2 u; } cv;
#define STORE_ROW(rr, aa)                                             \
    if (row0 + rr < NN) {                                             \
        cv.h[0] = __floats2half2_rn(aa.x, aa.y);                      \
        cv.h[1] = __floats2half2_rn(aa.z, aa.w);                      \
        ((uint2*)g_Y)[(row0 + rr) * 32 + tx] = cv.u;                  \
    }
    STORE_ROW(0, a0) STORE_ROW(1, a1) STORE_ROW(2, a2) STORE_ROW(3, a3)
#undef STORE_ROW
}

// ---------------- histogram (8/thread) + n2 run boundaries + n2 tail fill ----------------
__global__ __launch_bounds__(256) void hist_kernel(const int* __restrict__ hi1,
                                                   const int* __restrict__ hi2,
                                                   int nnz1, int nnz2, int B2h) {
    if (blockIdx.x < B2h) {
        int gid = blockIdx.x * 256 + threadIdx.x;

        // distributed n2ptr tail fill: nodes beyond the last present node -> nnz2
        int last = __ldg(&hi2[nnz2 - 1]);  // broadcast (L2/L1 cached)
        if (gid < NN - last) g_n2ptr[last + 1 + gid] = nnz2;

        int i = gid * 8;
        if (i >= nnz2) return;
        int lim = (i + 8 <= nnz2) ? 8 : (nnz2 - i);
        int e[8], nd[8];
#pragma unroll
        for (int u = 0; u < 8; u++) {
            if (u < lim) {
                e[u] = __ldg(&hi2[nnz2 + i + u]);
                nd[u] = __ldg(&hi2[i + u]);
            }
        }
#pragma unroll
        for (int u = 0; u < 8; u++) {
            if (u < lim) atomicAdd(&g_ecnt[(NE + e[u]) * PAD], 1);
        }
        int pv = (i == 0) ? -1 : __ldg(&hi2[i - 1]);
#pragma unroll
        for (int u = 0; u < 8; u++) {
            if (u < lim) {
                if (nd[u] != pv) {
                    for (int n = pv + 1; n <= nd[u]; n++) g_n2ptr[n] = i + u;
                }
                pv = nd[u];
            }
        }
    } else {
        int k = (blockIdx.x - B2h) * 256 + threadIdx.x;
        if (k >= nnz1) return;
        int node = __ldg(&hi1[k]), edge = __ldg(&hi1[nnz1 + k]);
        atomicAdd(&g_ecnt[edge * PAD], 1);
        atomicAdd(&g_n1cnt[node * PAD], 1);
    }
}

// ---------------- exclusive scans (4 elems/thread) + counter re-zero ----------------
__device__ __forceinline__ void block_scan4(int* cnt, int* ptr, int* pos, int n) {
    __shared__ int wsum[32];
    __shared__ int s_tot;
    int t = threadIdx.x, lane = t & 31, wid = t >> 5;
    int carry = 0;
    for (int base = 0; base < n; base += 4096) {
        int i0 = base + t * 4;
        int v[4];
#pragma unroll
        for (int u = 0; u < 4; u++) {
            int i = i0 + u;
            v[u] = (i < n) ? cnt[i * PAD] : 0;
            if (i < n) cnt[i * PAD] = 0;  // re-zero for next call (maintains invariant)
        }
        int tsum = v[0] + v[1] + v[2] + v[3];
        int inc = tsum;
#pragma unroll
        for (int o = 1; o < 32; o <<= 1) {
            int u = __shfl_up_sync(~0u, inc, o);
            if (lane >= o) inc += u;
        }
        if (lane == 31) wsum[wid] = inc;
        __syncthreads();
        if (wid == 0) {
            int w = wsum[lane];
            int wi = w;
#pragma unroll
            for (int o = 1; o < 32; o <<= 1) {
                int u = __shfl_up_sync(~0u, wi, o);
                if (lane >= o) wi += u;
            }
            wsum[lane] = wi - w;
            if (lane == 31) s_tot = wi;
        }
        __syncthreads();
        int run = carry + wsum[wid] + (inc - tsum);
#pragma unroll
        for (int u = 0; u < 4; u++) {
            int i = i0 + u;
            if (i < n) { ptr[i] = run; pos[i * PAD] = run; }
            run += v[u];
        }
        carry += s_tot;
        __syncthreads();
    }
    if (t == 0) ptr[n] = carry;
}

__global__ void scan_kernel() {
    if (blockIdx.x == 0) block_scan4(g_ecnt, g_eptr, g_epos, 2 * NE);
    else block_scan4(g_n1cnt, g_n1ptr, g_n1pos, NN);
}

// ---------------- fill CSR (lean, batched 8/thread) ----------------
__global__ __launch_bounds__(256) void fill_kernel(const int* __restrict__ hi1,
                                                   const int* __restrict__ hi2,
                                                   int nnz1, int nnz2, int B2f) {
    if (blockIdx.x < B2f) {
        int i = (blockIdx.x * 256 + threadIdx.x) * 8;
        if (i >= nnz2) return;
        if (i + 8 <= nnz2) {
            int nd[8], e[8], p[8];
#pragma unroll
            for (int u = 0; u < 8; u++) {
                nd[u] = __ldg(&hi2[i + u]);
                e[u] = __ldg(&hi2[nnz2 + i + u]);
            }
#pragma unroll
            for (int u = 0; u < 8; u++) p[u] = atomicAdd(&g_epos[(NE + e[u]) * PAD], 1);
#pragma unroll
            for (int u = 0; u < 8; u++) g_emem[p[u]] = nd[u];
        } else {
            for (int u = i; u < nnz2; u++) {
                int n0 = __ldg(&hi2[u]), e0 = __ldg(&hi2[nnz2 + u]);
                int p = atomicAdd(&g_epos[(NE + e0) * PAD], 1);
                g_emem[p] = n0;
            }
        }
    } else {
        int k = (blockIdx.x - B2f) * 256 + threadIdx.x;
        if (k >= nnz1) return;
        int node = __ldg(&hi1[k]), edge = __ldg(&hi1[nnz1 + k]);
        int p = atomicAdd(&g_epos[edge * PAD], 1);
        int q = atomicAdd(&g_n1pos[node * PAD], 1);
        g_emem[p] = node;
        g_nmem1[q] = edge;
    }
}

// ---------------- per-edge-slot mean (warp per slot) ----------------
__global__ void edge_mean_kernel() {
    int w = (blockIdx.x * 256 + threadIdx.x) >> 5;
    int lane = threadIdx.x & 31;
    if (w >= 2 * NE) return;
    int beg = g_eptr[w], end = g_eptr[w + 1];
    int col = ((w >= NE) ? 32 : 0) + lane;
    const __half2* Y2 = (const __half2*)g_Y;
    float sx = 0.f, sy = 0.f;
    int j = beg;
    for (; j + 8 <= end; j += 8) {
        float2 f[8];
#pragma unroll
        for (int u = 0; u < 8; u++) {
            int n0 = g_emem[j + u];
            f[u] = __half22float2(Y2[n0 * 64 + col]);
        }
#pragma unroll
        for (int u = 0; u < 8; u++) { sx += f[u].x; sy += f[u].y; }
    }
    for (; j < end; j++) {
        int n0 = g_emem[j];
        float2 a = __half22float2(Y2[n0 * 64 + col]);
        sx += a.x;
        sy += a.y;
    }
    int cnt = end - beg;
    float inv = 1.f / (float)(cnt > 0 ? cnt : 1);
    ((__half2*)g_emean)[w * 32 + lane] = __floats2half2_rn(sx * inv, sy * inv);
}

// ---------------- per-node output (warp per node) ----------------
__global__ void node_out_kernel(const int* __restrict__ hi2, int nnz2,
                                const float* __restrict__ bout, float* __restrict__ out) {
    int w = (blockIdx.x * 256 + threadIdx.x) >> 5;
    int lane = threadIdx.x & 31;
    if (w >= NN) return;
    const __half2* E2 = (const __half2*)g_emean;
    const int* hi2e = hi2 + nnz2;
    float sx = 0.f, sy = 0.f;

    {
        int beg = g_n1ptr[w], end = g_n1ptr[w + 1];
        int j = beg;
        for (; j + 4 <= end; j += 4) {
            float2 f[4];
#pragma unroll
            for (int u = 0; u < 4; u++) {
                int e = g_nmem1[j + u];
                f[u] = __half22float2(E2[e * 32 + lane]);
            }
#pragma unroll
            for (int u = 0; u < 4; u++) { sx += f[u].x; sy += f[u].y; }
        }
        for (; j < end; j++) {
            int e = g_nmem1[j];
            float2 a = __half22float2(E2[e * 32 + lane]);
            sx += a.x;
            sy += a.y;
        }
    }
    {
        int beg = g_n2ptr[w], end = g_n2ptr[w + 1];
        int j = beg;
        for (; j + 8 <= end; j += 8) {
            float2 f[8];
#pragma unroll
            for (int u = 0; u < 8; u++) {
                int e = __ldg(&hi2e[j + u]);
                f[u] = __half22float2(E2[(NE + e) * 32 + lane]);
            }
#pragma unroll
            for (int u = 0; u < 8; u++) { sx += f[u].x; sy += f[u].y; }
        }
        for (; j < end; j++) {
            int e = __ldg(&hi2e[j]);
            float2 a = __half22float2(E2[(NE + e) * 32 + lane]);
            sx += a.x;
            sy += a.y;
        }
    }
    float2 bo = ((const float2*)bout)[lane];
    ((float2*)out)[w * 32 + lane] = make_float2(bo.x + 0.5f * sx, bo.y + 0.5f * sy);
}

// ---------------- launcher: forked-stream DAG ----------------
extern "C" void kernel_launch(void* const* d_in, const int* in_sizes, int n_in,
                              void* d_out, int out_size) {
    const float* x = (const float*)d_in[0];
    const int* hi1 = (const int*)d_in[1];
    const int* hi2 = (const int*)d_in[2];
    const float* W1 = (const float*)d_in[3];
    const float* b1 = (const float*)d_in[4];
    const float* W2 = (const float*)d_in[5];
    const float* b2 = (const float*)d_in[6];
    const float* Wout = (const float*)d_in[7];
    const float* bout = (const float*)d_in[8];
    float* out = (float*)d_out;

    int nnz1 = in_sizes[1] / 2;
    int nnz2 = in_sizes[2] / 2;

    // Fork: side branch computes fold -> gemm (independent of CSR build)
    cudaEventRecord(hx.ev_fork, 0);
    cudaStreamWaitEvent(hx.side, hx.ev_fork, 0);
    fold_kernel<<<65, 256, 0, hx.side>>>(W1, b1, W2, b2, Wout);
    gemm_kernel<<<GEMM_BLOCKS, 256, 0, hx.side>>>(x);
    cudaEventRecord(hx.ev_gemm, hx.side);

    // Main branch: CSR build (no zero kernel — counters re-zeroed by scan)
    int B2h = (nnz2 + 2047) / 2048;  // 8 entries/thread
    hist_kernel<<<B2h + (nnz1 + 255) / 256, 256>>>(hi1, hi2, nnz1, nnz2, B2h);
    scan_kernel<<<2, 1024>>>();
    int B2f = (nnz2 + 2047) / 2048;  // 8 entries/thread
    fill_kernel<<<B2f + (nnz1 + 255) / 256, 256>>>(hi1, hi2, nnz1, nnz2, B2f);

    // Join: gather stages need both Y (side) and CSR (main)
    cudaStreamWaitEvent(0, hx.ev_gemm, 0);
    edge_mean_kernel<<<(2 * NE * 32 + 255) / 256, 256>>>();
    node_out_kernel<<<(NN * 32 + 255) / 256, 256>>>(hi2, nnz2, bout, out);
}

// round 10
// speedup vs baseline: 1.0985x; 1.0985x over previous
#include <cuda_runtime.h>
#include <cuda_fp16.h>

#define NN 10000
#define NE 4000
#define MAXM (4 * 1024 * 1024)
#define PAD 64  // 256B stride between atomic counters -> spreads across all LTS slices

// scan layout: 512 counters per block
#define EBLKS 16   // ceil(2*NE / 512)
#define NBLKS 20   // ceil(NN / 512)

// ---------------- device scratch (zero-initialized at module load) ----------------
__device__ float g_VT[128 * 128];
__device__ float g_cc[128];
__device__ __half g_Y[NN * 128];
__device__ __half g_emean[2 * NE * 64];
__device__ int g_ecnt[2 * NE * PAD];   // zeroed by scan1 after reading (invariant)
__device__ int g_epos[2 * NE * PAD];
__device__ int g_eptr[2 * NE + 1];
__device__ int g_n1cnt[NN * PAD];      // zeroed by scan1 after reading (invariant)
__device__ int g_n1pos[NN * PAD];
__device__ int g_n1ptr[NN + 1];
__device__ int g_n2ptr[NN + 1];        // fully rewritten by hist each call
__device__ int g_emem[MAXM];
__device__ int g_nmem1[MAXM];
__device__ int g_bsumE[EBLKS];         // per-block totals (overwritten before read, each call)
__device__ int g_bsumN[NBLKS];

// ---------------- side-stream plumbing ----------------
struct HxPlumbing {
    cudaStream_t side;
    cudaEvent_t ev_fork, ev_gemm;
    HxPlumbing() {
        cudaStreamCreateWithFlags(&side, cudaStreamNonBlocking);
        cudaEventCreateWithFlags(&ev_fork, cudaEventDisableTiming);
        cudaEventCreateWithFlags(&ev_gemm, cudaEventDisableTiming);
    }
};
static HxPlumbing hx;

// ---------------- fold weights (side stream) ----------------
__global__ void fold_kernel(const float* __restrict__ W1, const float* __restrict__ b1,
                            const float* __restrict__ W2, const float* __restrict__ b2,
                            const float* __restrict__ Wout) {
    int bb = blockIdx.x;
    if (bb < 64) {
        int idx = bb * 256 + threadIdx.x;
        int j = idx >> 7, k = idx & 127;
        int s = j >> 6, jo = j & 63;
        const float* W = s ? W2 : W1;
        float sum = 0.f;
#pragma unroll 8
        for (int h = 0; h < 128; h++) sum = fmaf(Wout[jo * 128 + h], W[h * 128 + k], sum);
        g_VT[k * 128 + j] = sum;
    } else {
        int j = threadIdx.x;
        if (j < 128) {
            int s = j >> 6, jo = j & 63;
            const float* b = s ? b2 : b1;
            float sum = 0.f;
#pragma unroll 8
            for (int h = 0; h < 128; h++) sum = fmaf(Wout[jo * 128 + h], b[h], sum);
            g_cc[j] = sum;
        }
    }
}

// ---------------- GEMM (side stream): Y = x @ Vcat^T + cc, fp16 out ----------------
#define GEMM_BLOCKS ((NN + 31) / 32)  // 313

#define FMA4(a, sc, v)                 \
    a.x = fmaf(sc, v.x, a.x);          \
    a.y = fmaf(sc, v.y, a.y);          \
    a.z = fmaf(sc, v.z, a.z);          \
    a.w = fmaf(sc, v.w, a.w);

__global__ __launch_bounds__(256) void gemm_kernel(const float* __restrict__ x) {
    int tx = threadIdx.x & 31;
    int ty = threadIdx.x >> 5;
    int row0 = blockIdx.x * 32 + ty * 4;
    const float4* x4 = (const float4*)x;
    const float4* v4 = (const float4*)g_VT;

    int rb0 = (row0 + 0 < NN ? row0 + 0 : NN - 1) * 32;
    int rb1 = (row0 + 1 < NN ? row0 + 1 : NN - 1) * 32;
    int rb2 = (row0 + 2 < NN ? row0 + 2 : NN - 1) * 32;
    int rb3 = (row0 + 3 < NN ? row0 + 3 : NN - 1) * 32;

    float4 a0 = make_float4(0.f, 0.f, 0.f, 0.f), a1 = a0, a2 = a0, a3 = a0;

#pragma unroll 4
    for (int k4 = 0; k4 < 32; k4++) {
        float4 v0 = v4[(4 * k4 + 0) * 32 + tx];
        float4 v1 = v4[(4 * k4 + 1) * 32 + tx];
        float4 v2 = v4[(4 * k4 + 2) * 32 + tx];
        float4 v3 = v4[(4 * k4 + 3) * 32 + tx];
        float4 q;
        q = x4[rb0 + k4];
        FMA4(a0, q.x, v0); FMA4(a0, q.y, v1); FMA4(a0, q.z, v2); FMA4(a0, q.w, v3);
        q = x4[rb1 + k4];
        FMA4(a1, q.x, v0); FMA4(a1, q.y, v1); FMA4(a1, q.z, v2); FMA4(a1, q.w, v3);
        q = x4[rb2 + k4];
        FMA4(a2, q.x, v0); FMA4(a2, q.y, v1); FMA4(a2, q.z, v2); FMA4(a2, q.w, v3);
        q = x4[rb3 + k4];
        FMA4(a3, q.x, v0); FMA4(a3, q.y, v1); FMA4(a3, q.z, v2); FMA4(a3, q.w, v3);
    }
    float4 c = ((const float4*)g_cc)[tx];
    a0.x += c.x; a0.y += c.y; a0.z += c.z; a0.w += c.w;
    a1.x += c.x; a1.y += c.y; a1.z += c.z; a1.w += c.w;
    a2.x += c.x; a2.y += c.y; a2.z += c.z; a2.w += c.w;
    a3.x += c.x; a3.y += c.y; a3.z += c.z; a3.w += c.w;

    union { __half2 h[2]; uint2 u; } cv;
#define STORE_ROW(rr, aa)                                             \
    if (row0 + rr < NN) {                                             \
        cv.h[0] = __floats2half2_rn(aa.x, aa.y);                      \
        cv.h[1] = __floats2half2_rn(aa.z, aa.w);                      \
        ((uint2*)g_Y)[(row0 + rr) * 32 + tx] = cv.u;                  \
    }
    STORE_ROW(0, a0) STORE_ROW(1, a1) STORE_ROW(2, a2) STORE_ROW(3, a3)
#undef STORE_ROW
}

// ---------------- histogram (8/thread) + n2 run boundaries + n2 tail fill ----------------
__global__ __launch_bounds__(256) void hist_kernel(const int* __restrict__ hi1,
                                                   const int* __restrict__ hi2,
                                                   int nnz1, int nnz2, int B2h) {
    if (blockIdx.x < B2h) {
        int gid = blockIdx.x * 256 + threadIdx.x;

        int last = __ldg(&hi2[nnz2 - 1]);
        if (gid < NN - last) g_n2ptr[last + 1 + gid] = nnz2;

        int i = gid * 8;
        if (i >= nnz2) return;
        int lim = (i + 8 <= nnz2) ? 8 : (nnz2 - i);
        int e[8], nd[8];
#pragma unroll
        for (int u = 0; u < 8; u++) {
            if (u < lim) {
                e[u] = __ldg(&hi2[nnz2 + i + u]);
                nd[u] = __ldg(&hi2[i + u]);
            }
        }
#pragma unroll
        for (int u = 0; u < 8; u++) {
            if (u < lim) atomicAdd(&g_ecnt[(NE + e[u]) * PAD], 1);
        }
        int pv = (i == 0) ? -1 : __ldg(&hi2[i - 1]);
#pragma unroll
        for (int u = 0; u < 8; u++) {
            if (u < lim) {
                if (nd[u] != pv) {
                    for (int n = pv + 1; n <= nd[u]; n++) g_n2ptr[n] = i + u;
                }
                pv = nd[u];
            }
        }
    } else {
        int k = (blockIdx.x - B2h) * 256 + threadIdx.x;
        if (k >= nnz1) return;
        int node = __ldg(&hi1[k]), edge = __ldg(&hi1[nnz1 + k]);
        atomicAdd(&g_ecnt[edge * PAD], 1);
        atomicAdd(&g_n1cnt[node * PAD], 1);
    }
}

// ---------------- scan phase 1: per-block local scan + totals (36 blocks) ----------------
__global__ __launch_bounds__(512) void scan1_kernel() {
    __shared__ int wsum[16];
    int b = blockIdx.x;
    int *cnt, *ptr, *pos, *bsum;
    int n, base;
    if (b < EBLKS) { cnt = g_ecnt; ptr = g_eptr; pos = g_epos; n = 2 * NE; base = b * 512; bsum = &g_bsumE[b]; }
    else { cnt = g_n1cnt; ptr = g_n1ptr; pos = g_n1pos; n = NN; base = (b - EBLKS) * 512; bsum = &g_bsumN[b - EBLKS]; }

    int t = threadIdx.x, lane = t & 31, wid = t >> 5;
    int i = base + t;
    int v = (i < n) ? cnt[i * PAD] : 0;
    if (i < n) cnt[i * PAD] = 0;  // re-zero (maintains call-entry invariant)

    int inc = v;
#pragma unroll
    for (int o = 1; o < 32; o <<= 1) {
        int u = __shfl_up_sync(~0u, inc, o);
        if (lane >= o) inc += u;
    }
    if (lane == 31) wsum[wid] = inc;
    __syncthreads();
    if (wid == 0 && lane < 16) {
        int w = wsum[lane];
        int wi = w;
#pragma unroll
        for (int o = 1; o < 16; o <<= 1) {
            int u = __shfl_up_sync(0xffffu, wi, o);
            if (lane >= o) wi += u;
        }
        wsum[lane] = wi - w;  // exclusive warp offsets
    }
    __syncthreads();
    int excl = wsum[wid] + inc - v;
    if (i < n) { ptr[i] = excl; pos[i * PAD] = excl; }
    if (t == 511) *bsum = excl + v;  // block total (out-of-range v contribute 0)
}

// ---------------- scan phase 2: add block offsets (36 blocks) ----------------
__global__ __launch_bounds__(512) void scan2_kernel() {
    __shared__ int s_off;
    int b = blockIdx.x;
    int *ptr, *pos;
    const int* bs;
    int n, base, lb, nb;
    if (b < EBLKS) { ptr = g_eptr; pos = g_epos; n = 2 * NE; lb = b; nb = EBLKS; bs = g_bsumE; base = b * 512; }
    else { ptr = g_n1ptr; pos = g_n1pos; n = NN; lb = b - EBLKS; nb = NBLKS; bs = g_bsumN; base = lb * 512; }

    if (threadIdx.x < 32) {
        int lane = threadIdx.x;
        int vall = (lane < nb) ? bs[lane] : 0;
        int voff = (lane < lb) ? vall : 0;
        int off = __reduce_add_sync(0xffffffffu, voff);
        int full = __reduce_add_sync(0xffffffffu, vall);
        if (lane == 0) {
            s_off = off;
            if (lb == nb - 1) ptr[n] = full;
        }
    }
    __syncthreads();
    int off = s_off;
    int i = base + threadIdx.x;
    if (i < n) { ptr[i] += off; pos[i * PAD] += off; }
}

// ---------------- fill CSR (lean, batched 8/thread) ----------------
__global__ __launch_bounds__(256) void fill_kernel(const int* __restrict__ hi1,
                                                   const int* __restrict__ hi2,
                                                   int nnz1, int nnz2, int B2f) {
    if (blockIdx.x < B2f) {
        int i = (blockIdx.x * 256 + threadIdx.x) * 8;
        if (i >= nnz2) return;
        if (i + 8 <= nnz2) {
            int nd[8], e[8], p[8];
#pragma unroll
            for (int u = 0; u < 8; u++) {
                nd[u] = __ldg(&hi2[i + u]);
                e[u] = __ldg(&hi2[nnz2 + i + u]);
            }
#pragma unroll
            for (int u = 0; u < 8; u++) p[u] = atomicAdd(&g_epos[(NE + e[u]) * PAD], 1);
#pragma unroll
            for (int u = 0; u < 8; u++) g_emem[p[u]] = nd[u];
        } else {
            for (int u = i; u < nnz2; u++) {
                int n0 = __ldg(&hi2[u]), e0 = __ldg(&hi2[nnz2 + u]);
                int p = atomicAdd(&g_epos[(NE + e0) * PAD], 1);
                g_emem[p] = n0;
            }
        }
    } else {
        int k = (blockIdx.x - B2f) * 256 + threadIdx.x;
        if (k >= nnz1) return;
        int node = __ldg(&hi1[k]), edge = __ldg(&hi1[nnz1 + k]);
        int p = atomicAdd(&g_epos[edge * PAD], 1);
        int q = atomicAdd(&g_n1pos[node * PAD], 1);
        g_emem[p] = node;
        g_nmem1[q] = edge;
    }
}

// ---------------- per-edge-slot mean (warp per slot) ----------------
__global__ void edge_mean_kernel() {
    int w = (blockIdx.x * 256 + threadIdx.x) >> 5;
    int lane = threadIdx.x & 31;
    if (w >= 2 * NE) return;
    int beg = g_eptr[w], end = g_eptr[w + 1];
    int col = ((w >= NE) ? 32 : 0) + lane;
    const __half2* Y2 = (const __half2*)g_Y;
    float sx = 0.f, sy = 0.f;
    int j = beg;
    for (; j + 8 <= end; j += 8) {
        float2 f[8];
#pragma unroll
        for (int u = 0; u < 8; u++) {
            int n0 = g_emem[j + u];
            f[u] = __half22float2(Y2[n0 * 64 + col]);
        }
#pragma unroll
        for (int u = 0; u < 8; u++) { sx += f[u].x; sy += f[u].y; }
    }
    for (; j < end; j++) {
        int n0 = g_emem[j];
        float2 a = __half22float2(Y2[n0 * 64 + col]);
        sx += a.x;
        sy += a.y;
    }
    int cnt = end - beg;
    float inv = 1.f / (float)(cnt > 0 ? cnt : 1);
    ((__half2*)g_emean)[w * 32 + lane] = __floats2half2_rn(sx * inv, sy * inv);
}

// ---------------- per-node output (warp per node) ----------------
__global__ void node_out_kernel(const int* __restrict__ hi2, int nnz2,
                                const float* __restrict__ bout, float* __restrict__ out) {
    int w = (blockIdx.x * 256 + threadIdx.x) >> 5;
    int lane = threadIdx.x & 31;
    if (w >= NN) return;
    const __half2* E2 = (const __half2*)g_emean;
    const int* hi2e = hi2 + nnz2;
    float sx = 0.f, sy = 0.f;

    {
        int beg = g_n1ptr[w], end = g_n1ptr[w + 1];
        int j = beg;
        for (; j + 4 <= end; j += 4) {
            float2 f[4];
#pragma unroll
            for (int u = 0; u < 4; u++) {
                int e = g_nmem1[j + u];
                f[u] = __half22float2(E2[e * 32 + lane]);
            }
#pragma unroll
            for (int u = 0; u < 4; u++) { sx += f[u].x; sy += f[u].y; }
        }
        for (; j < end; j++) {
            int e = g_nmem1[j];
            float2 a = __half22float2(E2[e * 32 + lane]);
            sx += a.x;
            sy += a.y;
        }
    }
    {
        int beg = g_n2ptr[w], end = g_n2ptr[w + 1];
        int j = beg;
        for (; j + 8 <= end; j += 8) {
            float2 f[8];
#pragma unroll
            for (int u = 0; u < 8; u++) {
                int e = __ldg(&hi2e[j + u]);
                f[u] = __half22float2(E2[(NE + e) * 32 + lane]);
            }
#pragma unroll
            for (int u = 0; u < 8; u++) { sx += f[u].x; sy += f[u].y; }
        }
        for (; j < end; j++) {
            int e = __ldg(&hi2e[j]);
            float2 a = __half22float2(E2[(NE + e) * 32 + lane]);
            sx += a.x;
            sy += a.y;
        }
    }
    float2 bo = ((const float2*)bout)[lane];
    ((float2*)out)[w * 32 + lane] = make_float2(bo.x + 0.5f * sx, bo.y + 0.5f * sy);
}

// ---------------- launcher: forked-stream DAG ----------------
extern "C" void kernel_launch(void* const* d_in, const int* in_sizes, int n_in,
                              void* d_out, int out_size) {
    const float* x = (const float*)d_in[0];
    const int* hi1 = (const int*)d_in[1];
    const int* hi2 = (const int*)d_in[2];
    const float* W1 = (const float*)d_in[3];
    const float* b1 = (const float*)d_in[4];
    const float* W2 = (const float*)d_in[5];
    const float* b2 = (const float*)d_in[6];
    const float* Wout = (const float*)d_in[7];
    const float* bout = (const float*)d_in[8];
    float* out = (float*)d_out;

    int nnz1 = in_sizes[1] / 2;
    int nnz2 = in_sizes[2] / 2;

    // Fork: side branch computes fold -> gemm
    cudaEventRecord(hx.ev_fork, 0);
    cudaStreamWaitEvent(hx.side, hx.ev_fork, 0);
    fold_kernel<<<65, 256, 0, hx.side>>>(W1, b1, W2, b2, Wout);
    gemm_kernel<<<GEMM_BLOCKS, 256, 0, hx.side>>>(x);
    cudaEventRecord(hx.ev_gemm, hx.side);

    // Main branch: CSR build
    int B2h = (nnz2 + 2047) / 2048;
    hist_kernel<<<B2h + (nnz1 + 255) / 256, 256>>>(hi1, hi2, nnz1, nnz2, B2h);
    scan1_kernel<<<EBLKS + NBLKS, 512>>>();
    scan2_kernel<<<EBLKS + NBLKS, 512>>>();
    int B2f = (nnz2 + 2047) / 2048;
    fill_kernel<<<B2f + (nnz1 + 255) / 256, 256>>>(hi1, hi2, nnz1, nnz2, B2f);

    // Join: gather stages need both Y (side) and CSR (main)
    cudaStreamWaitEvent(0, hx.ev_gemm, 0);
    edge_mean_kernel<<<(2 * NE * 32 + 255) / 256, 256>>>();
    node_out_kernel<<<(NN * 32 + 255) / 256, 256>>>(hi2, nnz2, bout, out);
}